// round 1
// baseline (speedup 1.0000x reference)
#include <cuda_runtime.h>
#include <math.h>

// Problem constants
#define BB 4
#define SS 1024
#define DD 1024
#define HH 16
#define DKK 64

// ---------------- scratch (device globals; no allocations allowed) ----------
__device__ float g_pe[SS * DD];                 // sinusoidal pos emb   (4 MB)
__device__ float g_p [SS * DD];                 // pos emb @ Wp^T       (4 MB)
__device__ float g_q [BB * SS * DD];            // 16 MB
__device__ float g_k [BB * SS * DD];            // 16 MB
__device__ float g_v [BB * SS * DD];            // 16 MB
__device__ float g_cs[67108864];                // content scores / attn (256 MB)
__device__ float g_c2[67108864];                // raw pos scores        (256 MB)
__device__ float g_bu[BB * HH * SS];            // u . k  per (b,h,col)
__device__ float g_bv[HH * SS];                 // v . p  per (h,j)
__device__ float g_ctx[BB * SS * DD];           // 16 MB

// ---------------- pos emb ---------------------------------------------------
__global__ void posemb_kernel(float* __restrict__ pe) {
    int idx = blockIdx.x * blockDim.x + threadIdx.x;
    if (idx >= SS * (DD / 2)) return;
    int j = idx / (DD / 2);
    int i = idx - j * (DD / 2);
    // inv_freq = 10000 ^ (-(2i)/D)
    float t = (2.0f * (float)i) / (float)DD;
    float invf = expf(-t * 9.210340371976184f);   // ln(10000)
    float pos = (float)(SS - 1 - j);
    float x = pos * invf;
    float s, c;
    sincosf(x, &s, &c);
    pe[j * DD + i]          = s;
    pe[j * DD + i + DD / 2] = c;
}

// ---------------- bias vectors ----------------------------------------------
// bu[b,h,kk] = sum_d u[h,d] * k[b,kk,h*64+d]   (one warp per output)
__global__ void bias_uk(const float* __restrict__ kbuf, const float* __restrict__ u,
                        float* __restrict__ bu) {
    int gw   = (blockIdx.x * blockDim.x + threadIdx.x) >> 5;
    int lane = threadIdx.x & 31;
    if (gw >= BB * HH * SS) return;
    int kk = gw % SS;
    int h  = (gw / SS) % HH;
    int b  = gw / (SS * HH);
    const float* krow = kbuf + ((long)b * SS + kk) * DD + h * DKK;
    const float* uh   = u + h * DKK;
    float s = krow[lane] * uh[lane] + krow[lane + 32] * uh[lane + 32];
    #pragma unroll
    for (int o = 16; o; o >>= 1) s += __shfl_xor_sync(0xffffffffu, s, o);
    if (lane == 0) bu[gw] = s;
}

// bv[h,j] = sum_d v[h,d] * p[j, h*64+d]
__global__ void bias_vp(const float* __restrict__ pbuf, const float* __restrict__ vb,
                        float* __restrict__ bv) {
    int gw   = (blockIdx.x * blockDim.x + threadIdx.x) >> 5;
    int lane = threadIdx.x & 31;
    if (gw >= HH * SS) return;
    int j = gw % SS;
    int h = gw / SS;
    const float* prow = pbuf + (long)j * DD + h * DKK;
    const float* vh   = vb + h * DKK;
    float s = prow[lane] * vh[lane] + prow[lane + 32] * vh[lane + 32];
    #pragma unroll
    for (int o = 16; o; o >>= 1) s += __shfl_xor_sync(0xffffffffu, s, o);
    if (lane == 0) bv[gw] = s;
}

// ---------------- generic NT GEMM: C = A(MxK) * B(NxK)^T --------------------
// 128x128 block tile, BK=16, 256 threads, 8x8 per thread.
// Batched: z -> (b = z/Hdim, h = z%Hdim), per-axis strides.
// Requires M%128==0, N%128==0, K%16==0.
__global__ __launch_bounds__(256) void gemm_nt(
    const float* __restrict__ A, const float* __restrict__ Bm, float* __restrict__ C,
    int M, int N, int K, int lda, int ldb, int ldc,
    int Hdim, long sAb, long sAh, long sBb, long sBh, long sCb, long sCh)
{
    int z  = blockIdx.z;
    int bb = z / Hdim, hh = z - bb * Hdim;
    A  += bb * sAb + hh * sAh;
    Bm += bb * sBb + hh * sBh;
    C  += bb * sCb + hh * sCh;

    __shared__ float As[16][128 + 4];
    __shared__ float Bs[16][128 + 4];

    const int tid  = threadIdx.x;
    const int m0   = blockIdx.y * 128;
    const int n0   = blockIdx.x * 128;
    const int lrow = tid >> 2;          // 0..63
    const int lk4  = (tid & 3) * 4;     // 0,4,8,12
    const int ty   = tid >> 4;          // 0..15
    const int tx   = tid & 15;          // 0..15

    float acc[8][8] = {};

    for (int k0 = 0; k0 < K; k0 += 16) {
        #pragma unroll
        for (int r = 0; r < 2; r++) {
            int row = lrow + r * 64;
            float4 a = *(const float4*)(A + (long)(m0 + row) * lda + k0 + lk4);
            As[lk4 + 0][row] = a.x; As[lk4 + 1][row] = a.y;
            As[lk4 + 2][row] = a.z; As[lk4 + 3][row] = a.w;
            float4 b = *(const float4*)(Bm + (long)(n0 + row) * ldb + k0 + lk4);
            Bs[lk4 + 0][row] = b.x; Bs[lk4 + 1][row] = b.y;
            Bs[lk4 + 2][row] = b.z; Bs[lk4 + 3][row] = b.w;
        }
        __syncthreads();
        #pragma unroll
        for (int k = 0; k < 16; k++) {
            float4 a0 = *(const float4*)&As[k][ty * 8];
            float4 a1 = *(const float4*)&As[k][ty * 8 + 4];
            float4 b0 = *(const float4*)&Bs[k][tx * 8];
            float4 b1 = *(const float4*)&Bs[k][tx * 8 + 4];
            float av[8] = {a0.x, a0.y, a0.z, a0.w, a1.x, a1.y, a1.z, a1.w};
            float bv[8] = {b0.x, b0.y, b0.z, b0.w, b1.x, b1.y, b1.z, b1.w};
            #pragma unroll
            for (int i = 0; i < 8; i++)
                #pragma unroll
                for (int j = 0; j < 8; j++)
                    acc[i][j] = fmaf(av[i], bv[j], acc[i][j]);
        }
        __syncthreads();
    }
    #pragma unroll
    for (int i = 0; i < 8; i++) {
        long m = m0 + ty * 8 + i;
        float* crow = C + m * ldc + n0 + tx * 8;
        *(float4*)(crow)     = make_float4(acc[i][0], acc[i][1], acc[i][2], acc[i][3]);
        *(float4*)(crow + 4) = make_float4(acc[i][4], acc[i][5], acc[i][6], acc[i][7]);
    }
}

// ---------------- NN GEMM with N=64: C = A(MxK) * B(KxN) --------------------
// 128x64 block tile, BK=16, 256 threads, 8x4 per thread. M%128==0, K%16==0.
__global__ __launch_bounds__(256) void gemm_nn64(
    const float* __restrict__ A, const float* __restrict__ Bm, float* __restrict__ C,
    int M, int K, int lda, int ldb, int ldc,
    int Hdim, long sAb, long sAh, long sBb, long sBh, long sCb, long sCh)
{
    int z  = blockIdx.z;
    int bb = z / Hdim, hh = z - bb * Hdim;
    A  += bb * sAb + hh * sAh;
    Bm += bb * sBb + hh * sBh;
    C  += bb * sCb + hh * sCh;

    __shared__ float As[16][128 + 4];
    __shared__ float Bs[16][64 + 4];

    const int tid  = threadIdx.x;
    const int m0   = blockIdx.y * 128;
    const int lrow = tid >> 2;
    const int lk4  = (tid & 3) * 4;
    const int brow = tid >> 4;          // 0..15 (k within tile)
    const int bc4  = (tid & 15) * 4;    // col4
    const int ty   = tid >> 4;
    const int tx   = tid & 15;

    float acc[8][4] = {};

    for (int k0 = 0; k0 < K; k0 += 16) {
        #pragma unroll
        for (int r = 0; r < 2; r++) {
            int row = lrow + r * 64;
            float4 a = *(const float4*)(A + (long)(m0 + row) * lda + k0 + lk4);
            As[lk4 + 0][row] = a.x; As[lk4 + 1][row] = a.y;
            As[lk4 + 2][row] = a.z; As[lk4 + 3][row] = a.w;
        }
        {
            float4 b = *(const float4*)(Bm + (long)(k0 + brow) * ldb + bc4);
            *(float4*)&Bs[brow][bc4] = b;
        }
        __syncthreads();
        #pragma unroll
        for (int k = 0; k < 16; k++) {
            float4 a0 = *(const float4*)&As[k][ty * 8];
            float4 a1 = *(const float4*)&As[k][ty * 8 + 4];
            float4 b0 = *(const float4*)&Bs[k][tx * 4];
            float av[8] = {a0.x, a0.y, a0.z, a0.w, a1.x, a1.y, a1.z, a1.w};
            float bv[4] = {b0.x, b0.y, b0.z, b0.w};
            #pragma unroll
            for (int i = 0; i < 8; i++)
                #pragma unroll
                for (int j = 0; j < 4; j++)
                    acc[i][j] = fmaf(av[i], bv[j], acc[i][j]);
        }
        __syncthreads();
    }
    #pragma unroll
    for (int i = 0; i < 8; i++) {
        long m = m0 + ty * 8 + i;
        *(float4*)(C + m * ldc + tx * 4) =
            make_float4(acc[i][0], acc[i][1], acc[i][2], acc[i][3]);
    }
}

// ---------------- shift + combine + softmax (in-place over CS) --------------
// Rel-shift semantics (verified vs pad/reshape reference):
//   out[q,c] = PS[q, S-1-q+c]   if c <= q
//            = 0                 if c == q+1
//            = PS[q+1, c-q-2]    if c >  q+1
// where PS[q,j] = C2[q,j] + bv[h,j]. Mask is all-true -> no masking needed.
__global__ __launch_bounds__(256) void softmax_combine(
    float* __restrict__ cs_attn, const float* __restrict__ c2,
    const float* __restrict__ bu, const float* __restrict__ bv)
{
    const int q = blockIdx.x, h = blockIdx.y, b = blockIdx.z;
    const long base = ((long)(b * HH + h) * SS + q) * SS;
    float*       csrow = cs_attn + base;
    const float* psq   = c2 + base;
    const int    q1    = (q + 1 < SS) ? (q + 1) : (SS - 1);
    const float* psq1  = c2 + ((long)(b * HH + h) * SS + q1) * SS;
    const float* burow = bu + (long)(b * HH + h) * SS;
    const float* bvrow = bv + (long)h * SS;

    const int tid = threadIdx.x;
    float vals[4];
    float mx = -1e30f;
    #pragma unroll
    for (int i = 0; i < 4; i++) {
        int c = tid + i * 256;
        float ps;
        if (c <= q)            { int j = SS - 1 - q + c; ps = psq[j]  + bvrow[j]; }
        else if (c == q + 1)   { ps = 0.0f; }
        else                   { int j = c - q - 2;      ps = psq1[j] + bvrow[j]; }
        float s = (csrow[c] + burow[c] + ps) * 0.125f;   // 1/sqrt(64)
        vals[i] = s;
        mx = fmaxf(mx, s);
    }

    __shared__ float red[8];
    #pragma unroll
    for (int o = 16; o; o >>= 1) mx = fmaxf(mx, __shfl_xor_sync(0xffffffffu, mx, o));
    if ((tid & 31) == 0) red[tid >> 5] = mx;
    __syncthreads();
    if (tid < 32) {
        float m = (tid < 8) ? red[tid] : -1e30f;
        #pragma unroll
        for (int o = 16; o; o >>= 1) m = fmaxf(m, __shfl_xor_sync(0xffffffffu, m, o));
        if (tid == 0) red[0] = m;
    }
    __syncthreads();
    mx = red[0];

    float sum = 0.0f;
    #pragma unroll
    for (int i = 0; i < 4; i++) { vals[i] = expf(vals[i] - mx); sum += vals[i]; }

    __shared__ float red2[8];
    #pragma unroll
    for (int o = 16; o; o >>= 1) sum += __shfl_xor_sync(0xffffffffu, sum, o);
    if ((tid & 31) == 0) red2[tid >> 5] = sum;
    __syncthreads();
    if (tid < 32) {
        float s = (tid < 8) ? red2[tid] : 0.0f;
        #pragma unroll
        for (int o = 16; o; o >>= 1) s += __shfl_xor_sync(0xffffffffu, s, o);
        if (tid == 0) red2[0] = s;
    }
    __syncthreads();
    const float inv = 1.0f / red2[0];
    #pragma unroll
    for (int i = 0; i < 4; i++) csrow[tid + i * 256] = vals[i] * inv;
}

// ---------------- launch -----------------------------------------------------
extern "C" void kernel_launch(void* const* d_in, const int* in_sizes, int n_in,
                              void* d_out, int out_size)
{
    const float* query = (const float*)d_in[0];
    const float* key   = (const float*)d_in[1];
    const float* value = (const float*)d_in[2];
    // d_in[3] = mask (all-true in this problem; semantics verified no-op)
    const float* Wq = (const float*)d_in[4];
    const float* Wk = (const float*)d_in[5];
    const float* Wv = (const float*)d_in[6];
    const float* Wp = (const float*)d_in[7];
    const float* Wo = (const float*)d_in[8];
    const float* pu = (const float*)d_in[9];
    const float* pv = (const float*)d_in[10];
    float* out = (float*)d_out;

    float *pe, *pp, *pq, *pk, *pvv, *pcs, *pc2, *pbu, *pbv, *pctx;
    cudaGetSymbolAddress((void**)&pe,  g_pe);
    cudaGetSymbolAddress((void**)&pp,  g_p);
    cudaGetSymbolAddress((void**)&pq,  g_q);
    cudaGetSymbolAddress((void**)&pk,  g_k);
    cudaGetSymbolAddress((void**)&pvv, g_v);
    cudaGetSymbolAddress((void**)&pcs, g_cs);
    cudaGetSymbolAddress((void**)&pc2, g_c2);
    cudaGetSymbolAddress((void**)&pbu, g_bu);
    cudaGetSymbolAddress((void**)&pbv, g_bv);
    cudaGetSymbolAddress((void**)&pctx, g_ctx);

    // 1) sinusoidal position embeddings
    posemb_kernel<<<(SS * (DD / 2) + 255) / 256, 256>>>(pe);

    // 2) projections  (y = x @ W^T)
    dim3 gproj(DD / 128, (BB * SS) / 128, 1);
    gemm_nt<<<gproj, 256>>>(query, Wq, pq, BB * SS, DD, DD, DD, DD, DD, 1, 0, 0, 0, 0, 0, 0);
    gemm_nt<<<gproj, 256>>>(key,   Wk, pk, BB * SS, DD, DD, DD, DD, DD, 1, 0, 0, 0, 0, 0, 0);
    gemm_nt<<<gproj, 256>>>(value, Wv, pvv, BB * SS, DD, DD, DD, DD, DD, 1, 0, 0, 0, 0, 0, 0);
    dim3 gpp(DD / 128, SS / 128, 1);
    gemm_nt<<<gpp, 256>>>(pe, Wp, pp, SS, DD, DD, DD, DD, DD, 1, 0, 0, 0, 0, 0, 0);

    // 3) rank-1 bias vectors: (q+u).k = q.k + u.k ; (q+v).p = q.p + v.p
    bias_uk<<<(BB * HH * SS) / 8, 256>>>(pk, pu, pbu);
    bias_vp<<<(HH * SS) / 8, 256>>>(pp, pv, pbv);

    // 4) batched score GEMMs per (b,h): CS = q.k^T ; C2 = q.p^T   (K=64)
    dim3 gsc(SS / 128, SS / 128, BB * HH);
    gemm_nt<<<gsc, 256>>>(pq, pk, pcs, SS, SS, DKK, DD, DD, SS, HH,
                          (long)SS * DD, DKK, (long)SS * DD, DKK,
                          (long)HH * SS * SS, (long)SS * SS);
    gemm_nt<<<gsc, 256>>>(pq, pp, pc2, SS, SS, DKK, DD, DD, SS, HH,
                          (long)SS * DD, DKK, 0, DKK,
                          (long)HH * SS * SS, (long)SS * SS);

    // 5) rel-shift + bias combine + softmax (attn written in-place over CS)
    dim3 gsm(SS, HH, BB);
    softmax_combine<<<gsm, 256>>>(pcs, pc2, pbu, pbv);

    // 6) context = attn @ v  per (b,h)  (NN, N=64), stored as (b, s, h*64+d)
    dim3 gav(1, SS / 128, BB * HH);
    gemm_nn64<<<gav, 256>>>(pcs, pvv, pctx, SS, SS, SS, DD, DD, HH,
                            (long)HH * SS * SS, (long)SS * SS,
                            (long)SS * DD, DKK, (long)SS * DD, DKK);

    // 7) output projection: out = ctx @ Wo^T
    dim3 gout(DD / 128, (BB * SS) / 128, 1);
    gemm_nt<<<gout, 256>>>(pctx, Wo, out, BB * SS, DD, DD, DD, DD, DD, 1, 0, 0, 0, 0, 0, 0);
}

// round 2
// speedup vs baseline: 1.2526x; 1.2526x over previous
#include <cuda_runtime.h>
#include <cuda_bf16.h>
#include <mma.h>
#include <math.h>

using namespace nvcuda;

// Problem constants
#define BB 4
#define SS 1024
#define DD 1024
#define HH 16
#define DKK 64

// ---------------- scratch (device globals; no allocations allowed) ----------
__device__ float g_pe[SS * DD];
__device__ float g_p [SS * DD];
__device__ float g_q [BB * SS * DD];
__device__ float g_k [BB * SS * DD];
__device__ float g_v [BB * SS * DD];
__device__ float g_cs[67108864];                // content scores / attn (256 MB)
__device__ float g_c2[67108864];                // raw pos scores        (256 MB)
__device__ float g_bu[BB * HH * SS];
__device__ float g_bv[HH * SS];
__device__ float g_ctx[BB * SS * DD];

// ---------------- pos emb ---------------------------------------------------
__global__ void posemb_kernel(float* __restrict__ pe) {
    int idx = blockIdx.x * blockDim.x + threadIdx.x;
    if (idx >= SS * (DD / 2)) return;
    int j = idx / (DD / 2);
    int i = idx - j * (DD / 2);
    float t = (2.0f * (float)i) / (float)DD;
    float invf = expf(-t * 9.210340371976184f);   // ln(10000)
    float pos = (float)(SS - 1 - j);
    float x = pos * invf;
    float s, c;
    sincosf(x, &s, &c);
    pe[j * DD + i]          = s;
    pe[j * DD + i + DD / 2] = c;
}

// ---------------- bias vectors ----------------------------------------------
__global__ void bias_uk(const float* __restrict__ kbuf, const float* __restrict__ u,
                        float* __restrict__ bu) {
    int gw   = (blockIdx.x * blockDim.x + threadIdx.x) >> 5;
    int lane = threadIdx.x & 31;
    if (gw >= BB * HH * SS) return;
    int kk = gw % SS;
    int h  = (gw / SS) % HH;
    int b  = gw / (SS * HH);
    const float* krow = kbuf + ((long)b * SS + kk) * DD + h * DKK;
    const float* uh   = u + h * DKK;
    float s = krow[lane] * uh[lane] + krow[lane + 32] * uh[lane + 32];
    #pragma unroll
    for (int o = 16; o; o >>= 1) s += __shfl_xor_sync(0xffffffffu, s, o);
    if (lane == 0) bu[gw] = s;
}

__global__ void bias_vp(const float* __restrict__ pbuf, const float* __restrict__ vb,
                        float* __restrict__ bv) {
    int gw   = (blockIdx.x * blockDim.x + threadIdx.x) >> 5;
    int lane = threadIdx.x & 31;
    if (gw >= HH * SS) return;
    int j = gw % SS;
    int h = gw / SS;
    const float* prow = pbuf + (long)j * DD + h * DKK;
    const float* vh   = vb + h * DKK;
    float s = prow[lane] * vh[lane] + prow[lane + 32] * vh[lane + 32];
    #pragma unroll
    for (int o = 16; o; o >>= 1) s += __shfl_xor_sync(0xffffffffu, s, o);
    if (lane == 0) bv[gw] = s;
}

// ---------------- bf16 split helper -----------------------------------------
__device__ __forceinline__ void split_store4(float4 v, __nv_bfloat16* hp, __nv_bfloat16* lp) {
    float xs[4] = {v.x, v.y, v.z, v.w};
    #pragma unroll
    for (int t = 0; t < 4; t++) {
        __nv_bfloat16 h = __float2bfloat16(xs[t]);
        hp[t] = h;
        lp[t] = __float2bfloat16(xs[t] - __bfloat162float(h));
    }
}

// ---------------- NT GEMM, bf16-split tensor cores --------------------------
// C = A(MxK) * B(NxK)^T, fp32 in/out, internally Ah*Bh + Ah*Bl + Al*Bh.
// 128x128 block tile, BK=16, 256 threads (8 warps, 2x4 warp grid, 64x32 warp tile).
// Register-staged double-buffered smem (one sync per k-tile).
// Requires M%128==0, N%128==0, K%16==0.
__global__ __launch_bounds__(256) void gemm_nt_bf16(
    const float* __restrict__ A, const float* __restrict__ Bm, float* __restrict__ C,
    int M, int N, int K, int lda, int ldb, int ldc,
    int Hdim, long sAb, long sAh, long sBb, long sBh, long sCb, long sCh)
{
    int z  = blockIdx.z;
    int bb = z / Hdim, hh = z - bb * Hdim;
    A  += bb * sAb + hh * sAh;
    Bm += bb * sBb + hh * sBh;
    C  += bb * sCb + hh * sCh;

    __shared__ __align__(32) __nv_bfloat16 Ah[2][128][16], Al[2][128][16];
    __shared__ __align__(32) __nv_bfloat16 Bh[2][128][16], Bl[2][128][16];

    const int tid  = threadIdx.x;
    const int m0   = blockIdx.y * 128;
    const int n0   = blockIdx.x * 128;
    const int lrow = tid >> 2;          // 0..63
    const int lk4  = (tid & 3) * 4;     // 0,4,8,12
    const int w    = tid >> 5;
    const int wm   = w >> 2;            // 0..1
    const int wn   = w & 3;             // 0..3

    wmma::fragment<wmma::accumulator, 16, 16, 16, float> acc[4][2];
    #pragma unroll
    for (int i = 0; i < 4; i++)
        #pragma unroll
        for (int j = 0; j < 2; j++) wmma::fill_fragment(acc[i][j], 0.0f);

    const int nt = K / 16;

    // preload tile 0
    {
        float4 sa0 = *(const float4*)(A  + (long)(m0 + lrow)      * lda + lk4);
        float4 sa1 = *(const float4*)(A  + (long)(m0 + lrow + 64) * lda + lk4);
        float4 sb0 = *(const float4*)(Bm + (long)(n0 + lrow)      * ldb + lk4);
        float4 sb1 = *(const float4*)(Bm + (long)(n0 + lrow + 64) * ldb + lk4);
        split_store4(sa0, &Ah[0][lrow][lk4],      &Al[0][lrow][lk4]);
        split_store4(sa1, &Ah[0][lrow + 64][lk4], &Al[0][lrow + 64][lk4]);
        split_store4(sb0, &Bh[0][lrow][lk4],      &Bl[0][lrow][lk4]);
        split_store4(sb1, &Bh[0][lrow + 64][lk4], &Bl[0][lrow + 64][lk4]);
    }
    __syncthreads();

    for (int kt = 0; kt < nt; kt++) {
        const int cur = kt & 1;
        float4 sa0, sa1, sb0, sb1;
        const bool pf = (kt + 1 < nt);
        if (pf) {
            int k0 = (kt + 1) * 16;
            sa0 = *(const float4*)(A  + (long)(m0 + lrow)      * lda + k0 + lk4);
            sa1 = *(const float4*)(A  + (long)(m0 + lrow + 64) * lda + k0 + lk4);
            sb0 = *(const float4*)(Bm + (long)(n0 + lrow)      * ldb + k0 + lk4);
            sb1 = *(const float4*)(Bm + (long)(n0 + lrow + 64) * ldb + k0 + lk4);
        }

        wmma::fragment<wmma::matrix_a, 16, 16, 16, __nv_bfloat16, wmma::row_major> fah[4], fal[4];
        wmma::fragment<wmma::matrix_b, 16, 16, 16, __nv_bfloat16, wmma::col_major> fbh[2], fbl[2];
        #pragma unroll
        for (int i = 0; i < 4; i++) {
            wmma::load_matrix_sync(fah[i], &Ah[cur][wm * 64 + i * 16][0], 16);
            wmma::load_matrix_sync(fal[i], &Al[cur][wm * 64 + i * 16][0], 16);
        }
        #pragma unroll
        for (int j = 0; j < 2; j++) {
            wmma::load_matrix_sync(fbh[j], &Bh[cur][wn * 32 + j * 16][0], 16);
            wmma::load_matrix_sync(fbl[j], &Bl[cur][wn * 32 + j * 16][0], 16);
        }
        #pragma unroll
        for (int i = 0; i < 4; i++)
            #pragma unroll
            for (int j = 0; j < 2; j++) {
                wmma::mma_sync(acc[i][j], fah[i], fbh[j], acc[i][j]);
                wmma::mma_sync(acc[i][j], fah[i], fbl[j], acc[i][j]);
                wmma::mma_sync(acc[i][j], fal[i], fbh[j], acc[i][j]);
            }

        if (pf) {
            const int nb = cur ^ 1;
            split_store4(sa0, &Ah[nb][lrow][lk4],      &Al[nb][lrow][lk4]);
            split_store4(sa1, &Ah[nb][lrow + 64][lk4], &Al[nb][lrow + 64][lk4]);
            split_store4(sb0, &Bh[nb][lrow][lk4],      &Bl[nb][lrow][lk4]);
            split_store4(sb1, &Bh[nb][lrow + 64][lk4], &Bl[nb][lrow + 64][lk4]);
        }
        __syncthreads();
    }

    #pragma unroll
    for (int i = 0; i < 4; i++)
        #pragma unroll
        for (int j = 0; j < 2; j++)
            wmma::store_matrix_sync(C + (long)(m0 + wm * 64 + i * 16) * ldc + n0 + wn * 32 + j * 16,
                                    acc[i][j], ldc, wmma::mem_row_major);
}

// ---------------- NN GEMM N=64, bf16-split tensor cores ---------------------
// C = A(MxK) * B(KxN), 128x64 block tile, BK=16, 256 threads
// (8 warps, 4x2 warp grid, 32x32 warp tile).
__global__ __launch_bounds__(256) void gemm_nn64_bf16(
    const float* __restrict__ A, const float* __restrict__ Bm, float* __restrict__ C,
    int M, int K, int lda, int ldb, int ldc,
    int Hdim, long sAb, long sAh, long sBb, long sBh, long sCb, long sCh)
{
    int z  = blockIdx.z;
    int bb = z / Hdim, hh = z - bb * Hdim;
    A  += bb * sAb + hh * sAh;
    Bm += bb * sBb + hh * sBh;
    C  += bb * sCb + hh * sCh;

    __shared__ __align__(32) __nv_bfloat16 Ah[2][128][16], Al[2][128][16];
    __shared__ __align__(32) __nv_bfloat16 Bh[2][16][64],  Bl[2][16][64];

    const int tid  = threadIdx.x;
    const int m0   = blockIdx.y * 128;
    const int lrow = tid >> 2;          // 0..63
    const int lk4  = (tid & 3) * 4;
    const int brow = tid >> 4;          // 0..15
    const int bc4  = (tid & 15) * 4;
    const int w    = tid >> 5;
    const int wm   = w >> 1;            // 0..3
    const int wn   = w & 1;             // 0..1

    wmma::fragment<wmma::accumulator, 16, 16, 16, float> acc[2][2];
    #pragma unroll
    for (int i = 0; i < 2; i++)
        #pragma unroll
        for (int j = 0; j < 2; j++) wmma::fill_fragment(acc[i][j], 0.0f);

    const int nt = K / 16;

    {
        float4 sa0 = *(const float4*)(A  + (long)(m0 + lrow)      * lda + lk4);
        float4 sa1 = *(const float4*)(A  + (long)(m0 + lrow + 64) * lda + lk4);
        float4 sb0 = *(const float4*)(Bm + (long)brow * ldb + bc4);
        split_store4(sa0, &Ah[0][lrow][lk4],      &Al[0][lrow][lk4]);
        split_store4(sa1, &Ah[0][lrow + 64][lk4], &Al[0][lrow + 64][lk4]);
        split_store4(sb0, &Bh[0][brow][bc4],      &Bl[0][brow][bc4]);
    }
    __syncthreads();

    for (int kt = 0; kt < nt; kt++) {
        const int cur = kt & 1;
        float4 sa0, sa1, sb0;
        const bool pf = (kt + 1 < nt);
        if (pf) {
            int k0 = (kt + 1) * 16;
            sa0 = *(const float4*)(A  + (long)(m0 + lrow)      * lda + k0 + lk4);
            sa1 = *(const float4*)(A  + (long)(m0 + lrow + 64) * lda + k0 + lk4);
            sb0 = *(const float4*)(Bm + (long)(k0 + brow) * ldb + bc4);
        }

        wmma::fragment<wmma::matrix_a, 16, 16, 16, __nv_bfloat16, wmma::row_major> fah[2], fal[2];
        wmma::fragment<wmma::matrix_b, 16, 16, 16, __nv_bfloat16, wmma::row_major> fbh[2], fbl[2];
        #pragma unroll
        for (int i = 0; i < 2; i++) {
            wmma::load_matrix_sync(fah[i], &Ah[cur][wm * 32 + i * 16][0], 16);
            wmma::load_matrix_sync(fal[i], &Al[cur][wm * 32 + i * 16][0], 16);
        }
        #pragma unroll
        for (int j = 0; j < 2; j++) {
            wmma::load_matrix_sync(fbh[j], &Bh[cur][0][wn * 32 + j * 16], 64);
            wmma::load_matrix_sync(fbl[j], &Bl[cur][0][wn * 32 + j * 16], 64);
        }
        #pragma unroll
        for (int i = 0; i < 2; i++)
            #pragma unroll
            for (int j = 0; j < 2; j++) {
                wmma::mma_sync(acc[i][j], fah[i], fbh[j], acc[i][j]);
                wmma::mma_sync(acc[i][j], fah[i], fbl[j], acc[i][j]);
                wmma::mma_sync(acc[i][j], fal[i], fbh[j], acc[i][j]);
            }

        if (pf) {
            const int nb = cur ^ 1;
            split_store4(sa0, &Ah[nb][lrow][lk4],      &Al[nb][lrow][lk4]);
            split_store4(sa1, &Ah[nb][lrow + 64][lk4], &Al[nb][lrow + 64][lk4]);
            split_store4(sb0, &Bh[nb][brow][bc4],      &Bl[nb][brow][bc4]);
        }
        __syncthreads();
    }

    #pragma unroll
    for (int i = 0; i < 2; i++)
        #pragma unroll
        for (int j = 0; j < 2; j++)
            wmma::store_matrix_sync(C + (long)(m0 + wm * 32 + i * 16) * ldc + wn * 32 + j * 16,
                                    acc[i][j], ldc, wmma::mem_row_major);
}

// ---------------- shift + combine + softmax (in-place over CS) --------------
__global__ __launch_bounds__(256) void softmax_combine(
    float* __restrict__ cs_attn, const float* __restrict__ c2,
    const float* __restrict__ bu, const float* __restrict__ bv)
{
    const int q = blockIdx.x, h = blockIdx.y, b = blockIdx.z;
    const long base = ((long)(b * HH + h) * SS + q) * SS;
    float*       csrow = cs_attn + base;
    const float* psq   = c2 + base;
    const int    q1    = (q + 1 < SS) ? (q + 1) : (SS - 1);
    const float* psq1  = c2 + ((long)(b * HH + h) * SS + q1) * SS;
    const float* burow = bu + (long)(b * HH + h) * SS;
    const float* bvrow = bv + (long)h * SS;

    const int tid = threadIdx.x;
    float vals[4];
    float mx = -1e30f;
    #pragma unroll
    for (int i = 0; i < 4; i++) {
        int c = tid + i * 256;
        float ps;
        if (c <= q)            { int j = SS - 1 - q + c; ps = psq[j]  + bvrow[j]; }
        else if (c == q + 1)   { ps = 0.0f; }
        else                   { int j = c - q - 2;      ps = psq1[j] + bvrow[j]; }
        float s = (csrow[c] + burow[c] + ps) * 0.125f;   // 1/sqrt(64)
        vals[i] = s;
        mx = fmaxf(mx, s);
    }

    __shared__ float red[8];
    #pragma unroll
    for (int o = 16; o; o >>= 1) mx = fmaxf(mx, __shfl_xor_sync(0xffffffffu, mx, o));
    if ((tid & 31) == 0) red[tid >> 5] = mx;
    __syncthreads();
    if (tid < 32) {
        float m = (tid < 8) ? red[tid] : -1e30f;
        #pragma unroll
        for (int o = 16; o; o >>= 1) m = fmaxf(m, __shfl_xor_sync(0xffffffffu, m, o));
        if (tid == 0) red[0] = m;
    }
    __syncthreads();
    mx = red[0];

    float sum = 0.0f;
    #pragma unroll
    for (int i = 0; i < 4; i++) { vals[i] = expf(vals[i] - mx); sum += vals[i]; }

    __shared__ float red2[8];
    #pragma unroll
    for (int o = 16; o; o >>= 1) sum += __shfl_xor_sync(0xffffffffu, sum, o);
    if ((tid & 31) == 0) red2[tid >> 5] = sum;
    __syncthreads();
    if (tid < 32) {
        float s = (tid < 8) ? red2[tid] : 0.0f;
        #pragma unroll
        for (int o = 16; o; o >>= 1) s += __shfl_xor_sync(0xffffffffu, s, o);
        if (tid == 0) red2[0] = s;
    }
    __syncthreads();
    const float inv = 1.0f / red2[0];
    #pragma unroll
    for (int i = 0; i < 4; i++) csrow[tid + i * 256] = vals[i] * inv;
}

// ---------------- launch -----------------------------------------------------
extern "C" void kernel_launch(void* const* d_in, const int* in_sizes, int n_in,
                              void* d_out, int out_size)
{
    const float* query = (const float*)d_in[0];
    const float* key   = (const float*)d_in[1];
    const float* value = (const float*)d_in[2];
    // d_in[3] = mask (all-true; no-op)
    const float* Wq = (const float*)d_in[4];
    const float* Wk = (const float*)d_in[5];
    const float* Wv = (const float*)d_in[6];
    const float* Wp = (const float*)d_in[7];
    const float* Wo = (const float*)d_in[8];
    const float* pu = (const float*)d_in[9];
    const float* pv = (const float*)d_in[10];
    float* out = (float*)d_out;

    float *pe, *pp, *pq, *pk, *pvv, *pcs, *pc2, *pbu, *pbv, *pctx;
    cudaGetSymbolAddress((void**)&pe,  g_pe);
    cudaGetSymbolAddress((void**)&pp,  g_p);
    cudaGetSymbolAddress((void**)&pq,  g_q);
    cudaGetSymbolAddress((void**)&pk,  g_k);
    cudaGetSymbolAddress((void**)&pvv, g_v);
    cudaGetSymbolAddress((void**)&pcs, g_cs);
    cudaGetSymbolAddress((void**)&pc2, g_c2);
    cudaGetSymbolAddress((void**)&pbu, g_bu);
    cudaGetSymbolAddress((void**)&pbv, g_bv);
    cudaGetSymbolAddress((void**)&pctx, g_ctx);

    // 1) sinusoidal position embeddings
    posemb_kernel<<<(SS * (DD / 2) + 255) / 256, 256>>>(pe);

    // 2) projections  (y = x @ W^T)  — tensor cores
    dim3 gproj(DD / 128, (BB * SS) / 128, 1);
    gemm_nt_bf16<<<gproj, 256>>>(query, Wq, pq,  BB * SS, DD, DD, DD, DD, DD, 1, 0, 0, 0, 0, 0, 0);
    gemm_nt_bf16<<<gproj, 256>>>(key,   Wk, pk,  BB * SS, DD, DD, DD, DD, DD, 1, 0, 0, 0, 0, 0, 0);
    gemm_nt_bf16<<<gproj, 256>>>(value, Wv, pvv, BB * SS, DD, DD, DD, DD, DD, 1, 0, 0, 0, 0, 0, 0);
    dim3 gpp(DD / 128, SS / 128, 1);
    gemm_nt_bf16<<<gpp, 256>>>(pe, Wp, pp, SS, DD, DD, DD, DD, DD, 1, 0, 0, 0, 0, 0, 0);

    // 3) rank-1 bias vectors
    bias_uk<<<(BB * HH * SS) / 8, 256>>>(pk, pu, pbu);
    bias_vp<<<(HH * SS) / 8, 256>>>(pp, pv, pbv);

    // 4) batched score GEMMs per (b,h): CS = q.k^T ; C2 = q.p^T   (K=64)
    dim3 gsc(SS / 128, SS / 128, BB * HH);
    gemm_nt_bf16<<<gsc, 256>>>(pq, pk, pcs, SS, SS, DKK, DD, DD, SS, HH,
                               (long)SS * DD, DKK, (long)SS * DD, DKK,
                               (long)HH * SS * SS, (long)SS * SS);
    gemm_nt_bf16<<<gsc, 256>>>(pq, pp, pc2, SS, SS, DKK, DD, DD, SS, HH,
                               (long)SS * DD, DKK, 0, DKK,
                               (long)HH * SS * SS, (long)SS * SS);

    // 5) rel-shift + bias combine + softmax (attn written in-place over CS)
    dim3 gsm(SS, HH, BB);
    softmax_combine<<<gsm, 256>>>(pcs, pc2, pbu, pbv);

    // 6) context = attn @ v  per (b,h)  (NN, N=64)
    dim3 gav(1, SS / 128, BB * HH);
    gemm_nn64_bf16<<<gav, 256>>>(pcs, pvv, pctx, SS, SS, SS, DD, DD, HH,
                                 (long)HH * SS * SS, (long)SS * SS,
                                 (long)SS * DD, DKK, (long)SS * DD, DKK);

    // 7) output projection: out = ctx @ Wo^T
    dim3 gout(DD / 128, (BB * SS) / 128, 1);
    gemm_nt_bf16<<<gout, 256>>>(pctx, Wo, out, BB * SS, DD, DD, DD, DD, DD, 1, 0, 0, 0, 0, 0, 0);
}

// round 4
// speedup vs baseline: 1.3495x; 1.0774x over previous
#include <cuda_runtime.h>
#include <cuda_bf16.h>
#include <mma.h>
#include <math.h>

using namespace nvcuda;

#define BB 4
#define SS 1024
#define DD 1024
#define HH 16
#define DKK 64

typedef __nv_bfloat16 bf16;

// ---------------- scratch (device globals) ----------------------------------
__device__ float g_pq [BB * SS * DD];
__device__ float g_pk [BB * SS * DD];
__device__ float g_pv [BB * SS * DD];
__device__ float g_pp [SS * DD];
__device__ float g_ctx[BB * SS * DD];
__device__ float g_cs [67108864];               // content scores (fp32, 256 MB)
__device__ float g_c2 [67108864];               // raw pos scores (fp32, 256 MB)
__device__ float g_bu [BB * HH * SS];
__device__ float g_bv [HH * SS];
__device__ bf16 g_qh[BB * SS * DD], g_ql[BB * SS * DD];
__device__ bf16 g_kh[BB * SS * DD], g_kl[BB * SS * DD];
__device__ bf16 g_vinh[BB * SS * DD], g_vinl[BB * SS * DD];
__device__ bf16 g_Wqh[DD * DD], g_Wql[DD * DD];
__device__ bf16 g_Wkh[DD * DD], g_Wkl[DD * DD];
__device__ bf16 g_Wvh[DD * DD], g_Wvl[DD * DD];
__device__ bf16 g_Wph[DD * DD], g_Wpl[DD * DD];
__device__ bf16 g_Woh[DD * DD], g_Wol[DD * DD];
__device__ bf16 g_peh[SS * DD], g_pel[SS * DD];
__device__ bf16 g_pqh[BB * SS * DD], g_pql[BB * SS * DD];
__device__ bf16 g_pkh[BB * SS * DD], g_pkl[BB * SS * DD];
__device__ bf16 g_pph[SS * DD],      g_ppl[SS * DD];
__device__ bf16 g_vh [BB * SS * DD], g_vl [BB * SS * DD];
__device__ bf16 g_ath[67108864], g_atl[67108864];   // attn hi/lo (128 MB each)
__device__ bf16 g_cxh[BB * SS * DD], g_cxl[BB * SS * DD];

// ---------------- elementwise split: fp32 -> bf16 hi + bf16 lo --------------
__global__ void split_kernel(const float* __restrict__ x,
                             bf16* __restrict__ hi, bf16* __restrict__ lo, int n4) {
    int i = blockIdx.x * blockDim.x + threadIdx.x;
    if (i >= n4) return;
    float4 v = ((const float4*)x)[i];
    float f[4] = {v.x, v.y, v.z, v.w};
    bf16 h[4], l[4];
    #pragma unroll
    for (int t = 0; t < 4; t++) {
        h[t] = __float2bfloat16(f[t]);
        l[t] = __float2bfloat16(f[t] - __bfloat162float(h[t]));
    }
    ((uint2*)hi)[i] = *(uint2*)h;
    ((uint2*)lo)[i] = *(uint2*)l;
}

// ---------------- pos emb (writes hi/lo bf16 directly) ----------------------
__global__ void posemb_kernel(bf16* __restrict__ peh, bf16* __restrict__ pel) {
    int idx = blockIdx.x * blockDim.x + threadIdx.x;
    if (idx >= SS * (DD / 2)) return;
    int j = idx / (DD / 2);
    int i = idx - j * (DD / 2);
    float t = (2.0f * (float)i) / (float)DD;
    float invf = expf(-t * 9.210340371976184f);
    float pos = (float)(SS - 1 - j);
    float s, c;
    sincosf(pos * invf, &s, &c);
    bf16 sh = __float2bfloat16(s);
    bf16 ch = __float2bfloat16(c);
    peh[j * DD + i]          = sh;
    pel[j * DD + i]          = __float2bfloat16(s - __bfloat162float(sh));
    peh[j * DD + i + DD / 2] = ch;
    pel[j * DD + i + DD / 2] = __float2bfloat16(c - __bfloat162float(ch));
}

// ---------------- bias vectors (fp32 sources) --------------------------------
__global__ void bias_uk(const float* __restrict__ kbuf, const float* __restrict__ u,
                        float* __restrict__ bu) {
    int gw   = (blockIdx.x * blockDim.x + threadIdx.x) >> 5;
    int lane = threadIdx.x & 31;
    if (gw >= BB * HH * SS) return;
    int kk = gw % SS;
    int h  = (gw / SS) % HH;
    int b  = gw / (SS * HH);
    const float* krow = kbuf + ((long)b * SS + kk) * DD + h * DKK;
    const float* uh   = u + h * DKK;
    float s = krow[lane] * uh[lane] + krow[lane + 32] * uh[lane + 32];
    #pragma unroll
    for (int o = 16; o; o >>= 1) s += __shfl_xor_sync(0xffffffffu, s, o);
    if (lane == 0) bu[gw] = s;
}

__global__ void bias_vp(const float* __restrict__ pbuf, const float* __restrict__ vb,
                        float* __restrict__ bv) {
    int gw   = (blockIdx.x * blockDim.x + threadIdx.x) >> 5;
    int lane = threadIdx.x & 31;
    if (gw >= HH * SS) return;
    int j = gw % SS;
    int h = gw / SS;
    const float* prow = pbuf + (long)j * DD + h * DKK;
    const float* vh   = vb + h * DKK;
    float s = prow[lane] * vh[lane] + prow[lane + 32] * vh[lane + 32];
    #pragma unroll
    for (int o = 16; o; o >>= 1) s += __shfl_xor_sync(0xffffffffu, s, o);
    if (lane == 0) bv[gw] = s;
}

// ---------------- NT GEMM on pre-split bf16: C = A * B^T (fp32 out) ---------
// 128x128 CTA tile, BK=16 double-buffered, 256 thr (8 warps, 2x4, 64x32/warp).
__global__ __launch_bounds__(256, 2) void gemm_nt_s(
    const bf16* __restrict__ Ahg, const bf16* __restrict__ Alg,
    const bf16* __restrict__ Bhg, const bf16* __restrict__ Blg,
    float* __restrict__ C, int K, int lda, int ldb, int ldc,
    int Hdim, long strAb, long strAh, long strBb, long strBh, long strCb, long strCh)
{
    int z  = blockIdx.z;
    int bb = z / Hdim, hh = z - bb * Hdim;
    Ahg += bb * strAb + hh * strAh;  Alg += bb * strAb + hh * strAh;
    Bhg += bb * strBb + hh * strBh;  Blg += bb * strBb + hh * strBh;
    C   += bb * strCb + hh * strCh;

    __shared__ __align__(16) bf16 smAh[2][128][16], smAl[2][128][16];
    __shared__ __align__(16) bf16 smBh[2][128][16], smBl[2][128][16];

    const int tid  = threadIdx.x;
    const int m0   = blockIdx.y * 128;
    const int n0   = blockIdx.x * 128;
    const int lrow = tid >> 1;           // 0..127
    const int lc8  = (tid & 1) * 8;      // 0 or 8
    const int w    = tid >> 5;
    const int wm   = w >> 2;             // 0..1
    const int wn   = w & 3;              // 0..3

    const bf16* ah = Ahg + (long)(m0 + lrow) * lda + lc8;
    const bf16* al = Alg + (long)(m0 + lrow) * lda + lc8;
    const bf16* bh = Bhg + (long)(n0 + lrow) * ldb + lc8;
    const bf16* bl = Blg + (long)(n0 + lrow) * ldb + lc8;

    wmma::fragment<wmma::accumulator, 16, 16, 16, float> acc[4][2];
    #pragma unroll
    for (int i = 0; i < 4; i++)
        #pragma unroll
        for (int j = 0; j < 2; j++) wmma::fill_fragment(acc[i][j], 0.0f);

    const int nt = K / 16;

    *(uint4*)&smAh[0][lrow][lc8] = *(const uint4*)ah;
    *(uint4*)&smAl[0][lrow][lc8] = *(const uint4*)al;
    *(uint4*)&smBh[0][lrow][lc8] = *(const uint4*)bh;
    *(uint4*)&smBl[0][lrow][lc8] = *(const uint4*)bl;
    __syncthreads();

    for (int kt = 0; kt < nt; kt++) {
        const int cur = kt & 1;
        uint4 ra_h, ra_l, rb_h, rb_l;
        const bool pf = (kt + 1 < nt);
        if (pf) {
            int k0 = (kt + 1) * 16;
            ra_h = *(const uint4*)(ah + k0);
            ra_l = *(const uint4*)(al + k0);
            rb_h = *(const uint4*)(bh + k0);
            rb_l = *(const uint4*)(bl + k0);
        }

        {
            wmma::fragment<wmma::matrix_a, 16, 16, 16, bf16, wmma::row_major> fa[4];
            wmma::fragment<wmma::matrix_b, 16, 16, 16, bf16, wmma::col_major> fbh[2], fbl[2];
            #pragma unroll
            for (int i = 0; i < 4; i++)
                wmma::load_matrix_sync(fa[i], &smAh[cur][wm * 64 + i * 16][0], 16);
            #pragma unroll
            for (int j = 0; j < 2; j++) {
                wmma::load_matrix_sync(fbh[j], &smBh[cur][wn * 32 + j * 16][0], 16);
                wmma::load_matrix_sync(fbl[j], &smBl[cur][wn * 32 + j * 16][0], 16);
            }
            #pragma unroll
            for (int i = 0; i < 4; i++)
                #pragma unroll
                for (int j = 0; j < 2; j++) {
                    wmma::mma_sync(acc[i][j], fa[i], fbh[j], acc[i][j]);
                    wmma::mma_sync(acc[i][j], fa[i], fbl[j], acc[i][j]);
                }
            #pragma unroll
            for (int i = 0; i < 4; i++)
                wmma::load_matrix_sync(fa[i], &smAl[cur][wm * 64 + i * 16][0], 16);
            #pragma unroll
            for (int i = 0; i < 4; i++)
                #pragma unroll
                for (int j = 0; j < 2; j++)
                    wmma::mma_sync(acc[i][j], fa[i], fbh[j], acc[i][j]);
        }

        if (pf) {
            const int nb = cur ^ 1;
            *(uint4*)&smAh[nb][lrow][lc8] = ra_h;
            *(uint4*)&smAl[nb][lrow][lc8] = ra_l;
            *(uint4*)&smBh[nb][lrow][lc8] = rb_h;
            *(uint4*)&smBl[nb][lrow][lc8] = rb_l;
        }
        __syncthreads();
    }

    #pragma unroll
    for (int i = 0; i < 4; i++)
        #pragma unroll
        for (int j = 0; j < 2; j++)
            wmma::store_matrix_sync(C + (long)(m0 + wm * 64 + i * 16) * ldc + n0 + wn * 32 + j * 16,
                                    acc[i][j], ldc, wmma::mem_row_major);
}

// ---------------- NN GEMM N=64 on pre-split bf16 (fp32 out) -----------------
// 128x64 CTA tile, BK=16 double-buffered, 256 thr (8 warps, 4x2, 32x32/warp).
__global__ __launch_bounds__(256, 2) void gemm_nn64_s(
    const bf16* __restrict__ Ahg, const bf16* __restrict__ Alg,
    const bf16* __restrict__ Bhg, const bf16* __restrict__ Blg,
    float* __restrict__ C, int K, int lda, int ldb, int ldc,
    int Hdim, long strAb, long strAh, long strBb, long strBh, long strCb, long strCh)
{
    int z  = blockIdx.z;
    int bb = z / Hdim, hh = z - bb * Hdim;
    Ahg += bb * strAb + hh * strAh;  Alg += bb * strAb + hh * strAh;
    Bhg += bb * strBb + hh * strBh;  Blg += bb * strBb + hh * strBh;
    C   += bb * strCb + hh * strCh;

    __shared__ __align__(16) bf16 smAh[2][128][16], smAl[2][128][16];
    __shared__ __align__(16) bf16 smBh[2][16][64],  smBl[2][16][64];

    const int tid  = threadIdx.x;
    const int m0   = blockIdx.y * 128;
    const int lrow = tid >> 1;           // 0..127 (A rows)
    const int lc8  = (tid & 1) * 8;
    const int brow = tid >> 4;           // 0..15  (B rows)
    const int bc4  = (tid & 15) * 4;     // 0..60
    const int w    = tid >> 5;
    const int wm   = w >> 1;             // 0..3
    const int wn   = w & 1;              // 0..1

    const bf16* ah = Ahg + (long)(m0 + lrow) * lda + lc8;
    const bf16* al = Alg + (long)(m0 + lrow) * lda + lc8;
    const bf16* bh = Bhg + (long)brow * ldb + bc4;
    const bf16* bl = Blg + (long)brow * ldb + bc4;

    wmma::fragment<wmma::accumulator, 16, 16, 16, float> acc[2][2];
    #pragma unroll
    for (int i = 0; i < 2; i++)
        #pragma unroll
        for (int j = 0; j < 2; j++) wmma::fill_fragment(acc[i][j], 0.0f);

    const int nt = K / 16;

    *(uint4*)&smAh[0][lrow][lc8] = *(const uint4*)ah;
    *(uint4*)&smAl[0][lrow][lc8] = *(const uint4*)al;
    *(uint2*)&smBh[0][brow][bc4] = *(const uint2*)bh;
    *(uint2*)&smBl[0][brow][bc4] = *(const uint2*)bl;
    __syncthreads();

    for (int kt = 0; kt < nt; kt++) {
        const int cur = kt & 1;
        uint4 ra_h, ra_l; uint2 rb_h, rb_l;
        const bool pf = (kt + 1 < nt);
        if (pf) {
            long k0 = (long)(kt + 1) * 16;
            ra_h = *(const uint4*)(ah + k0);
            ra_l = *(const uint4*)(al + k0);
            rb_h = *(const uint2*)(bh + k0 * ldb);
            rb_l = *(const uint2*)(bl + k0 * ldb);
        }

        {
            wmma::fragment<wmma::matrix_a, 16, 16, 16, bf16, wmma::row_major> fa[2];
            wmma::fragment<wmma::matrix_b, 16, 16, 16, bf16, wmma::row_major> fbh[2], fbl[2];
            #pragma unroll
            for (int i = 0; i < 2; i++)
                wmma::load_matrix_sync(fa[i], &smAh[cur][wm * 32 + i * 16][0], 16);
            #pragma unroll
            for (int j = 0; j < 2; j++) {
                wmma::load_matrix_sync(fbh[j], &smBh[cur][0][wn * 32 + j * 16], 64);
                wmma::load_matrix_sync(fbl[j], &smBl[cur][0][wn * 32 + j * 16], 64);
            }
            #pragma unroll
            for (int i = 0; i < 2; i++)
                #pragma unroll
                for (int j = 0; j < 2; j++) {
                    wmma::mma_sync(acc[i][j], fa[i], fbh[j], acc[i][j]);
                    wmma::mma_sync(acc[i][j], fa[i], fbl[j], acc[i][j]);
                }
            #pragma unroll
            for (int i = 0; i < 2; i++)
                wmma::load_matrix_sync(fa[i], &smAl[cur][wm * 32 + i * 16][0], 16);
            #pragma unroll
            for (int i = 0; i < 2; i++)
                #pragma unroll
                for (int j = 0; j < 2; j++)
                    wmma::mma_sync(acc[i][j], fa[i], fbh[j], acc[i][j]);
        }

        if (pf) {
            const int nb = cur ^ 1;
            *(uint4*)&smAh[nb][lrow][lc8] = ra_h;
            *(uint4*)&smAl[nb][lrow][lc8] = ra_l;
            *(uint2*)&smBh[nb][brow][bc4] = rb_h;
            *(uint2*)&smBl[nb][brow][bc4] = rb_l;
        }
        __syncthreads();
    }

    #pragma unroll
    for (int i = 0; i < 2; i++)
        #pragma unroll
        for (int j = 0; j < 2; j++)
            wmma::store_matrix_sync(C + (long)(m0 + wm * 32 + i * 16) * ldc + wn * 32 + j * 16,
                                    acc[i][j], ldc, wmma::mem_row_major);
}

// ---------------- shift + combine + softmax -> attn bf16 hi/lo --------------
__global__ __launch_bounds__(256) void softmax_combine(
    const float* __restrict__ cs, const float* __restrict__ c2,
    const float* __restrict__ bu, const float* __restrict__ bv,
    bf16* __restrict__ ath, bf16* __restrict__ atl)
{
    const int q = blockIdx.x, h = blockIdx.y, b = blockIdx.z;
    const long base = ((long)(b * HH + h) * SS + q) * SS;
    const float* csrow = cs + base;
    const float* psq   = c2 + base;
    const int    q1    = (q + 1 < SS) ? (q + 1) : (SS - 1);
    const float* psq1  = c2 + ((long)(b * HH + h) * SS + q1) * SS;
    const float* burow = bu + (long)(b * HH + h) * SS;
    const float* bvrow = bv + (long)h * SS;

    const int tid = threadIdx.x;
    float vals[4];
    float mx = -1e30f;
    #pragma unroll
    for (int i = 0; i < 4; i++) {
        int c = tid + i * 256;
        float ps;
        if (c <= q)            { int j = SS - 1 - q + c; ps = psq[j]  + bvrow[j]; }
        else if (c == q + 1)   { ps = 0.0f; }
        else                   { int j = c - q - 2;      ps = psq1[j] + bvrow[j]; }
        float s = (csrow[c] + burow[c] + ps) * 0.125f;
        vals[i] = s;
        mx = fmaxf(mx, s);
    }

    __shared__ float red[8];
    #pragma unroll
    for (int o = 16; o; o >>= 1) mx = fmaxf(mx, __shfl_xor_sync(0xffffffffu, mx, o));
    if ((tid & 31) == 0) red[tid >> 5] = mx;
    __syncthreads();
    if (tid < 32) {
        float m = (tid < 8) ? red[tid] : -1e30f;
        #pragma unroll
        for (int o = 16; o; o >>= 1) m = fmaxf(m, __shfl_xor_sync(0xffffffffu, m, o));
        if (tid == 0) red[0] = m;
    }
    __syncthreads();
    mx = red[0];

    float sum = 0.0f;
    #pragma unroll
    for (int i = 0; i < 4; i++) { vals[i] = expf(vals[i] - mx); sum += vals[i]; }

    __shared__ float red2[8];
    #pragma unroll
    for (int o = 16; o; o >>= 1) sum += __shfl_xor_sync(0xffffffffu, sum, o);
    if ((tid & 31) == 0) red2[tid >> 5] = sum;
    __syncthreads();
    if (tid < 32) {
        float s = (tid < 8) ? red2[tid] : 0.0f;
        #pragma unroll
        for (int o = 16; o; o >>= 1) s += __shfl_xor_sync(0xffffffffu, s, o);
        if (tid == 0) red2[0] = s;
    }
    __syncthreads();
    const float inv = 1.0f / red2[0];
    #pragma unroll
    for (int i = 0; i < 4; i++) {
        float p = vals[i] * inv;
        bf16 ph = __float2bfloat16(p);
        ath[base + tid + i * 256] = ph;
        atl[base + tid + i * 256] = __float2bfloat16(p - __bfloat162float(ph));
    }
}

// ---------------- launch -----------------------------------------------------
extern "C" void kernel_launch(void* const* d_in, const int* in_sizes, int n_in,
                              void* d_out, int out_size)
{
    const float* query = (const float*)d_in[0];
    const float* key   = (const float*)d_in[1];
    const float* value = (const float*)d_in[2];
    // d_in[3] = mask (all-true; no-op)
    const float* Wq = (const float*)d_in[4];
    const float* Wk = (const float*)d_in[5];
    const float* Wv = (const float*)d_in[6];
    const float* Wp = (const float*)d_in[7];
    const float* Wo = (const float*)d_in[8];
    const float* pu = (const float*)d_in[9];
    const float* pv = (const float*)d_in[10];
    float* out = (float*)d_out;

    float *ppq, *ppk, *ppv, *ppp, *pctx, *pcs, *pc2, *pbu, *pbv;
    cudaGetSymbolAddress((void**)&ppq,  g_pq);
    cudaGetSymbolAddress((void**)&ppk,  g_pk);
    cudaGetSymbolAddress((void**)&ppv,  g_pv);
    cudaGetSymbolAddress((void**)&ppp,  g_pp);
    cudaGetSymbolAddress((void**)&pctx, g_ctx);
    cudaGetSymbolAddress((void**)&pcs,  g_cs);
    cudaGetSymbolAddress((void**)&pc2,  g_c2);
    cudaGetSymbolAddress((void**)&pbu,  g_bu);
    cudaGetSymbolAddress((void**)&pbv,  g_bv);

    bf16 *qh,*ql,*kh,*kl,*vinh,*vinl,*Wqh,*Wql,*Wkh,*Wkl,*Wvh,*Wvl,*Wph,*Wpl,*Woh,*Wol;
    bf16 *peh,*pel,*pqh,*pql,*pkh,*pkl,*pph,*ppl,*vh,*vl,*ath,*atl,*cxh,*cxl;
    cudaGetSymbolAddress((void**)&qh, g_qh);   cudaGetSymbolAddress((void**)&ql, g_ql);
    cudaGetSymbolAddress((void**)&kh, g_kh);   cudaGetSymbolAddress((void**)&kl, g_kl);
    cudaGetSymbolAddress((void**)&vinh, g_vinh); cudaGetSymbolAddress((void**)&vinl, g_vinl);
    cudaGetSymbolAddress((void**)&Wqh, g_Wqh); cudaGetSymbolAddress((void**)&Wql, g_Wql);
    cudaGetSymbolAddress((void**)&Wkh, g_Wkh); cudaGetSymbolAddress((void**)&Wkl, g_Wkl);
    cudaGetSymbolAddress((void**)&Wvh, g_Wvh); cudaGetSymbolAddress((void**)&Wvl, g_Wvl);
    cudaGetSymbolAddress((void**)&Wph, g_Wph); cudaGetSymbolAddress((void**)&Wpl, g_Wpl);
    cudaGetSymbolAddress((void**)&Woh, g_Woh); cudaGetSymbolAddress((void**)&Wol, g_Wol);
    cudaGetSymbolAddress((void**)&peh, g_peh); cudaGetSymbolAddress((void**)&pel, g_pel);
    cudaGetSymbolAddress((void**)&pqh, g_pqh); cudaGetSymbolAddress((void**)&pql, g_pql);
    cudaGetSymbolAddress((void**)&pkh, g_pkh); cudaGetSymbolAddress((void**)&pkl, g_pkl);
    cudaGetSymbolAddress((void**)&pph, g_pph); cudaGetSymbolAddress((void**)&ppl, g_ppl);
    cudaGetSymbolAddress((void**)&vh,  g_vh);  cudaGetSymbolAddress((void**)&vl,  g_vl);
    cudaGetSymbolAddress((void**)&ath, g_ath); cudaGetSymbolAddress((void**)&atl, g_atl);
    cudaGetSymbolAddress((void**)&cxh, g_cxh); cudaGetSymbolAddress((void**)&cxl, g_cxl);

    const int NB = BB * SS * DD;   // 4M
    const int NW = DD * DD;        // 1M

    // 1) pos emb (hi/lo) + input/weight splits
    posemb_kernel<<<(SS * (DD / 2) + 255) / 256, 256>>>(peh, pel);
    split_kernel<<<NB / 1024, 256>>>(query, qh, ql, NB / 4);
    split_kernel<<<NB / 1024, 256>>>(key,   kh, kl, NB / 4);
    split_kernel<<<NB / 1024, 256>>>(value, vinh, vinl, NB / 4);
    split_kernel<<<NW / 1024, 256>>>(Wq, Wqh, Wql, NW / 4);
    split_kernel<<<NW / 1024, 256>>>(Wk, Wkh, Wkl, NW / 4);
    split_kernel<<<NW / 1024, 256>>>(Wv, Wvh, Wvl, NW / 4);
    split_kernel<<<NW / 1024, 256>>>(Wp, Wph, Wpl, NW / 4);
    split_kernel<<<NW / 1024, 256>>>(Wo, Woh, Wol, NW / 4);

    // 2) projections (fp32 out)
    dim3 gproj(DD / 128, (BB * SS) / 128, 1);
    gemm_nt_s<<<gproj, 256>>>(qh, ql, Wqh, Wql, ppq, DD, DD, DD, DD, 1, 0, 0, 0, 0, 0, 0);
    gemm_nt_s<<<gproj, 256>>>(kh, kl, Wkh, Wkl, ppk, DD, DD, DD, DD, 1, 0, 0, 0, 0, 0, 0);
    gemm_nt_s<<<gproj, 256>>>(vinh, vinl, Wvh, Wvl, ppv, DD, DD, DD, DD, 1, 0, 0, 0, 0, 0, 0);
    dim3 gpp(DD / 128, SS / 128, 1);
    gemm_nt_s<<<gpp, 256>>>(peh, pel, Wph, Wpl, ppp, DD, DD, DD, DD, 1, 0, 0, 0, 0, 0, 0);

    // 3) split projection outputs + bias vectors
    split_kernel<<<NB / 1024, 256>>>(ppq, pqh, pql, NB / 4);
    split_kernel<<<NB / 1024, 256>>>(ppk, pkh, pkl, NB / 4);
    split_kernel<<<NB / 1024, 256>>>(ppv, vh,  vl,  NB / 4);
    split_kernel<<<NW / 1024, 256>>>(ppp, pph, ppl, NW / 4);
    bias_uk<<<(BB * HH * SS) / 8, 256>>>(ppk, pu, pbu);
    bias_vp<<<(HH * SS) / 8, 256>>>(ppp, pv, pbv);

    // 4) batched score GEMMs per (b,h): CS = q.k^T ; C2 = q.p^T  (K=64)
    dim3 gsc(SS / 128, SS / 128, BB * HH);
    gemm_nt_s<<<gsc, 256>>>(pqh, pql, pkh, pkl, pcs, DKK, DD, DD, SS, HH,
                            (long)SS * DD, DKK, (long)SS * DD, DKK,
                            (long)HH * SS * SS, (long)SS * SS);
    gemm_nt_s<<<gsc, 256>>>(pqh, pql, pph, ppl, pc2, DKK, DD, DD, SS, HH,
                            (long)SS * DD, DKK, 0, DKK,
                            (long)HH * SS * SS, (long)SS * SS);

    // 5) rel-shift + bias combine + softmax -> attn bf16 hi/lo
    dim3 gsm(SS, HH, BB);
    softmax_combine<<<gsm, 256>>>(pcs, pc2, pbu, pbv, ath, atl);

    // 6) context = attn @ v per (b,h)  (fp32 out, layout (b, s, h*64+d))
    dim3 gav(1, SS / 128, BB * HH);
    gemm_nn64_s<<<gav, 256>>>(ath, atl, vh, vl, pctx, SS, SS, DD, DD, HH,
                              (long)HH * SS * SS, (long)SS * SS,
                              (long)SS * DD, DKK, (long)SS * DD, DKK);

    // 7) split ctx, output projection
    split_kernel<<<NB / 1024, 256>>>(pctx, cxh, cxl, NB / 4);
    dim3 gout(DD / 128, (BB * SS) / 128, 1);
    gemm_nt_s<<<gout, 256>>>(cxh, cxl, Woh, Wol, out, DD, DD, DD, DD, 1, 0, 0, 0, 0, 0, 0);
}